// round 11
// baseline (speedup 1.0000x reference)
#include <cuda_runtime.h>
#include <cuda_fp16.h>

#define NN 50000
#define EE 1600000
#define CC 48
#define SS 10
#define DB 512   // degree histogram buckets

// Scratch (allocation-free: __device__ globals)
__device__ float  g_deg[NN];
__device__ int    g_cnt[NN];
__device__ int    g_off[NN + 4];     // padded for int4 stores
__device__ int    g_pos[NN];
__device__ float2 g_csc[EE];         // {src_as_float, p}
__device__ __half g_hA[NN * CC];     // fp16 feature rows (96 B/row)
__device__ __half g_hB[NN * CC];
__device__ int    g_dhist[DB];
__device__ int    g_dpos[DB];
__device__ int    g_perm[NN];        // nodes sorted by in-degree

// ---------- pass 1: src-degree (for norm) + dst-count (for CSC) ----------
__global__ void count_deg_kernel(const int* __restrict__ ei,
                                 const float* __restrict__ ea) {
    int e = blockIdx.x * blockDim.x + threadIdx.x;
    if (e < EE) {
        atomicAdd(&g_deg[ei[e]], ea[e]);      // row = source
        atomicAdd(&g_cnt[ei[EE + e]], 1);     // col = dest
    }
}

// ---------- pass 2: single-block exclusive scan, 4 elems/thread ----------
__global__ void scan_kernel() {
    __shared__ int warp_sums[32];
    __shared__ int s_carry;
    int tid = threadIdx.x;
    int lane = tid & 31, wid = tid >> 5;
    if (tid == 0) s_carry = 0;
    __syncthreads();

    for (int base = 0; base < NN; base += 4096) {
        int idx = base + tid * 4;
        int4 v = make_int4(0, 0, 0, 0);
        if (idx < NN) v = reinterpret_cast<const int4*>(g_cnt)[idx >> 2];
        int s0 = v.x;
        int s01 = s0 + v.y;
        int s012 = s01 + v.z;
        int tot = s012 + v.w;
        int x = tot;
        #pragma unroll
        for (int o = 1; o < 32; o <<= 1) {
            int y = __shfl_up_sync(0xFFFFFFFF, x, o);
            if (lane >= o) x += y;
        }
        if (lane == 31) warp_sums[wid] = x;
        __syncthreads();
        if (wid == 0) {
            int w = warp_sums[lane];
            #pragma unroll
            for (int o = 1; o < 32; o <<= 1) {
                int y = __shfl_up_sync(0xFFFFFFFF, w, o);
                if (lane >= o) w += y;
            }
            warp_sums[lane] = w;
        }
        __syncthreads();
        int excl = x - tot + (wid > 0 ? warp_sums[wid - 1] : 0);
        int e0 = s_carry + excl;
        if (idx < NN) {
            int4 outs = make_int4(e0, e0 + s0, e0 + s01, e0 + s012);
            reinterpret_cast<int4*>(g_off)[idx >> 2] = outs;
            reinterpret_cast<int4*>(g_pos)[idx >> 2] = outs;
        }
        __syncthreads();
        if (tid == 1023) s_carry += warp_sums[31];
        __syncthreads();
    }
    if (tid == 0) g_off[NN] = s_carry;
}

// ---------- pass 3: build CSC (norm folded in) ----------
__global__ void build_csc_kernel(const int* __restrict__ ei,
                                 const float* __restrict__ ea) {
    int e = blockIdx.x * blockDim.x + threadIdx.x;
    if (e < EE) {
        int r = ei[e];
        int c = ei[EE + e];
        float p = ea[e] / fmaxf(g_deg[r], 1e-12f);
        int pos = atomicAdd(&g_pos[c], 1);
        g_csc[pos] = make_float2(__int_as_float(r), p);
    }
}

// ---------- degree-sort: histogram -> scan -> scatter perm ----------
__global__ void dhist_kernel() {
    int n = blockIdx.x * blockDim.x + threadIdx.x;
    if (n < NN) {
        int d = min(g_cnt[n], DB - 1);
        atomicAdd(&g_dhist[d], 1);
    }
}

__global__ void dscan_kernel() {   // 1 block, DB=512 threads
    __shared__ int ws[16];
    int tid = threadIdx.x;
    int lane = tid & 31, wid = tid >> 5;
    int v = g_dhist[tid];
    int x = v;
    #pragma unroll
    for (int o = 1; o < 32; o <<= 1) {
        int y = __shfl_up_sync(0xFFFFFFFF, x, o);
        if (lane >= o) x += y;
    }
    if (lane == 31) ws[wid] = x;
    __syncthreads();
    if (wid == 0 && lane < 16) {
        int w = ws[lane];
        #pragma unroll
        for (int o = 1; o < 16; o <<= 1) {
            int y = __shfl_up_sync(0xFFFF, w, o);
            if (lane >= o) w += y;
        }
        ws[lane] = w;
    }
    __syncthreads();
    g_dpos[tid] = x - v + (wid > 0 ? ws[wid - 1] : 0);
}

__global__ void dperm_kernel() {
    int n = blockIdx.x * blockDim.x + threadIdx.x;
    if (n < NN) {
        int d = min(g_cnt[n], DB - 1);
        int pos = atomicAdd(&g_dpos[d], 1);
        g_perm[pos] = n;
    }
}

__device__ __forceinline__ uint2 pack_half4(float4 a) {
    uint2 o;
    __half2 lo = __float22half2_rn(make_float2(a.x, a.y));
    __half2 hi = __float22half2_rn(make_float2(a.z, a.w));
    o.x = *reinterpret_cast<unsigned*>(&lo);
    o.y = *reinterpret_cast<unsigned*>(&hi);
    return o;
}

// ---------- step 0: h0 one-hot(target); gather target[src] directly ----------
__global__ void step0_kernel(const int* __restrict__ target,
                             __half* __restrict__ hdst,
                             float* __restrict__ out,
                             const float* __restrict__ weight) {
    int g = blockIdx.x * 16 + threadIdx.x / 12;
    int c4 = threadIdx.x % 12;
    if (g >= NN) return;
    int node = g_perm[g];
    int beg = g_off[node], end = g_off[node + 1];
    int cbase = c4 * 4;
    float4 acc = make_float4(0.f, 0.f, 0.f, 0.f);
    for (int j = beg; j < end; j++) {
        float2 ed = __ldg(&g_csc[j]);
        int src = __float_as_int(ed.x);
        float p = ed.y;
        int tc = __ldg(&target[src]);
        acc.x += (tc == cbase + 0) ? p : 0.f;
        acc.y += (tc == cbase + 1) ? p : 0.f;
        acc.z += (tc == cbase + 2) ? p : 0.f;
        acc.w += (tc == cbase + 3) ? p : 0.f;
    }
    reinterpret_cast<uint2*>(hdst + node * CC)[c4] = pack_half4(acc);
    float w0 = __ldg(&weight[(cbase + 0) * SS]);
    float w1 = __ldg(&weight[(cbase + 1) * SS]);
    float w2 = __ldg(&weight[(cbase + 2) * SS]);
    float w3 = __ldg(&weight[(cbase + 3) * SS]);
    float4 o;
    o.x = acc.x * w0; o.y = acc.y * w1; o.z = acc.z * w2; o.w = acc.w * w3;
    reinterpret_cast<float4*>(out + node * CC)[c4] = o;   // first write: no read
}

// ---------- steps 1..9: fp16 CSC gather SpMM, fp32 accumulate, fused axpy ----------
__global__ void gather_kernel(const __half* __restrict__ hsrc,
                              __half* __restrict__ hdst,
                              float* __restrict__ out,
                              const float* __restrict__ weight,
                              int s, int write_h) {
    int g = blockIdx.x * 16 + threadIdx.x / 12;
    int c4 = threadIdx.x % 12;
    if (g >= NN) return;
    int node = g_perm[g];
    int beg = g_off[node], end = g_off[node + 1];
    float4 acc = make_float4(0.f, 0.f, 0.f, 0.f);

    int j = beg;
    int npair = beg + (((end - beg) >> 1) << 1);
    for (; j < npair; j += 2) {
        float2 e0 = __ldg(&g_csc[j]);
        float2 e1 = __ldg(&g_csc[j + 1]);
        int s0 = __float_as_int(e0.x);
        int s1 = __float_as_int(e1.x);
        uint2 r0 = __ldg(reinterpret_cast<const uint2*>(hsrc + s0 * CC) + c4);
        uint2 r1 = __ldg(reinterpret_cast<const uint2*>(hsrc + s1 * CC) + c4);
        float2 a0 = __half22float2(*reinterpret_cast<__half2*>(&r0.x));
        float2 b0 = __half22float2(*reinterpret_cast<__half2*>(&r0.y));
        float2 a1 = __half22float2(*reinterpret_cast<__half2*>(&r1.x));
        float2 b1 = __half22float2(*reinterpret_cast<__half2*>(&r1.y));
        acc.x = fmaf(e0.y, a0.x, acc.x);
        acc.y = fmaf(e0.y, a0.y, acc.y);
        acc.z = fmaf(e0.y, b0.x, acc.z);
        acc.w = fmaf(e0.y, b0.y, acc.w);
        acc.x = fmaf(e1.y, a1.x, acc.x);
        acc.y = fmaf(e1.y, a1.y, acc.y);
        acc.z = fmaf(e1.y, b1.x, acc.z);
        acc.w = fmaf(e1.y, b1.y, acc.w);
    }
    if (j < end) {
        float2 ed = __ldg(&g_csc[j]);
        int src = __float_as_int(ed.x);
        uint2 raw = __ldg(reinterpret_cast<const uint2*>(hsrc + src * CC) + c4);
        float2 fa = __half22float2(*reinterpret_cast<__half2*>(&raw.x));
        float2 fb = __half22float2(*reinterpret_cast<__half2*>(&raw.y));
        acc.x = fmaf(ed.y, fa.x, acc.x);
        acc.y = fmaf(ed.y, fa.y, acc.y);
        acc.z = fmaf(ed.y, fb.x, acc.z);
        acc.w = fmaf(ed.y, fb.y, acc.w);
    }

    if (write_h)
        reinterpret_cast<uint2*>(hdst + node * CC)[c4] = pack_half4(acc);
    int cbase = c4 * 4;
    float w0 = __ldg(&weight[(cbase + 0) * SS + s]);
    float w1 = __ldg(&weight[(cbase + 1) * SS + s]);
    float w2 = __ldg(&weight[(cbase + 2) * SS + s]);
    float w3 = __ldg(&weight[(cbase + 3) * SS + s]);
    float4 o = reinterpret_cast<float4*>(out + node * CC)[c4];
    o.x += acc.x * w0; o.y += acc.y * w1; o.z += acc.z * w2; o.w += acc.w * w3;
    reinterpret_cast<float4*>(out + node * CC)[c4] = o;
}

extern "C" void kernel_launch(void* const* d_in, const int* in_sizes, int n_in,
                              void* d_out, int out_size) {
    const int*   ei     = (const int*)d_in[0];    // [2, E]
    const float* ea     = (const float*)d_in[1];  // [E]
    const int*   target = (const int*)d_in[2];    // [N]
    const float* weight = (const float*)d_in[3];  // [C, S]
    float* out = (float*)d_out;                   // [N, C]

    void* p_deg;  cudaGetSymbolAddress(&p_deg,  g_deg);
    void* p_cnt;  cudaGetSymbolAddress(&p_cnt,  g_cnt);
    void* p_hA;   cudaGetSymbolAddress(&p_hA,   g_hA);
    void* p_hB;   cudaGetSymbolAddress(&p_hB,   g_hB);
    void* p_dh;   cudaGetSymbolAddress(&p_dh,   g_dhist);

    cudaMemsetAsync(p_deg, 0, NN * sizeof(float), 0);
    cudaMemsetAsync(p_cnt, 0, NN * sizeof(int), 0);
    cudaMemsetAsync(p_dh,  0, DB * sizeof(int), 0);

    count_deg_kernel<<<(EE + 255) / 256, 256>>>(ei, ea);
    scan_kernel<<<1, 1024>>>();
    // degree sort (depends only on g_cnt) runs while build_csc also queues
    dhist_kernel<<<(NN + 255) / 256, 256>>>();
    dscan_kernel<<<1, DB>>>();
    dperm_kernel<<<(NN + 255) / 256, 256>>>();
    build_csc_kernel<<<(EE + 255) / 256, 256>>>(ei, ea);

    __half* hA = (__half*)p_hA;
    __half* hB = (__half*)p_hB;
    const int node_blocks = (NN + 15) / 16;

    step0_kernel<<<node_blocks, 192>>>(target, hA, out, weight);

    __half* hcur = hA;
    __half* hnxt = hB;
    for (int s = 1; s < SS; s++) {
        gather_kernel<<<node_blocks, 192>>>(hcur, hnxt, out, weight, s,
                                            (s < SS - 1) ? 1 : 0);
        __half* t = hcur; hcur = hnxt; hnxt = t;
    }
}

// round 12
// speedup vs baseline: 1.0758x; 1.0758x over previous
#include <cuda_runtime.h>
#include <cuda_fp16.h>

#define NN 50000
#define EE 1600000
#define CC 48
#define SS 10

// Scratch (allocation-free: __device__ globals)
__device__ float  g_deg[NN];
__device__ int    g_cnt[NN];
__device__ int    g_off[NN + 4];     // padded for int4 stores
__device__ int    g_pos[NN];
__device__ float2 g_csc[EE];         // {src_as_float, p}
__device__ float  g_h1f[NN * CC];    // fp32 step-1 accumulator (scattered in build)
__device__ __half g_hA[NN * CC];     // fp16 feature rows (96 B/row)
__device__ __half g_hB[NN * CC];

// ---------- pass 1: src-degree (for norm) + dst-count (for CSC), 2 edges/thread ----------
__global__ void count_deg_kernel(const int* __restrict__ ei,
                                 const float* __restrict__ ea) {
    int t = blockIdx.x * blockDim.x + threadIdx.x;
    int e = t * 2;
    if (e < EE) {
        int2   r2 = *reinterpret_cast<const int2*>(ei + e);
        int2   c2 = *reinterpret_cast<const int2*>(ei + EE + e);
        float2 a2 = *reinterpret_cast<const float2*>(ea + e);
        atomicAdd(&g_deg[r2.x], a2.x);
        atomicAdd(&g_deg[r2.y], a2.y);
        atomicAdd(&g_cnt[c2.x], 1);
        atomicAdd(&g_cnt[c2.y], 1);
    }
}

// ---------- pass 2: single-block exclusive scan, 4 elems/thread ----------
__global__ void scan_kernel() {
    __shared__ int warp_sums[32];
    __shared__ int s_carry;
    int tid = threadIdx.x;
    int lane = tid & 31, wid = tid >> 5;
    if (tid == 0) s_carry = 0;
    __syncthreads();

    for (int base = 0; base < NN; base += 4096) {
        int idx = base + tid * 4;
        int4 v = make_int4(0, 0, 0, 0);
        if (idx < NN) v = reinterpret_cast<const int4*>(g_cnt)[idx >> 2];
        int s0 = v.x;
        int s01 = s0 + v.y;
        int s012 = s01 + v.z;
        int tot = s012 + v.w;
        int x = tot;
        #pragma unroll
        for (int o = 1; o < 32; o <<= 1) {
            int y = __shfl_up_sync(0xFFFFFFFF, x, o);
            if (lane >= o) x += y;
        }
        if (lane == 31) warp_sums[wid] = x;
        __syncthreads();
        if (wid == 0) {
            int w = warp_sums[lane];
            #pragma unroll
            for (int o = 1; o < 32; o <<= 1) {
                int y = __shfl_up_sync(0xFFFFFFFF, w, o);
                if (lane >= o) w += y;
            }
            warp_sums[lane] = w;
        }
        __syncthreads();
        int excl = x - tot + (wid > 0 ? warp_sums[wid - 1] : 0);
        int e0 = s_carry + excl;
        if (idx < NN) {
            int4 outs = make_int4(e0, e0 + s0, e0 + s01, e0 + s012);
            reinterpret_cast<int4*>(g_off)[idx >> 2] = outs;
            reinterpret_cast<int4*>(g_pos)[idx >> 2] = outs;
        }
        __syncthreads();
        if (tid == 1023) s_carry += warp_sums[31];
        __syncthreads();
    }
    if (tid == 0) g_off[NN] = s_carry;
}

// ---------- pass 3: build CSC (norm folded in) + step-1 one-hot scatter ----------
__global__ void build_csc_kernel(const int* __restrict__ ei,
                                 const float* __restrict__ ea,
                                 const int* __restrict__ target) {
    int e = blockIdx.x * blockDim.x + threadIdx.x;
    if (e < EE) {
        int r = ei[e];
        int c = ei[EE + e];
        float p = ea[e] / fmaxf(g_deg[r], 1e-12f);
        int pos = atomicAdd(&g_pos[c], 1);
        g_csc[pos] = make_float2(__int_as_float(r), p);
        // step 1 landing mass: h1[c][target[r]] += p  (h0 is one-hot(target))
        int tc = __ldg(&target[r]);
        atomicAdd(&g_h1f[c * CC + tc], p);
    }
}

__device__ __forceinline__ uint2 pack_half4(float4 a) {
    uint2 o;
    __half2 lo = __float22half2_rn(make_float2(a.x, a.y));
    __half2 hi = __float22half2_rn(make_float2(a.z, a.w));
    o.x = *reinterpret_cast<unsigned*>(&lo);
    o.y = *reinterpret_cast<unsigned*>(&hi);
    return o;
}

// ---------- finalize step 1: h1f -> fp16 hA, out = h1f * w[:,0] ----------
__global__ void finalize0_kernel(__half* __restrict__ hdst,
                                 float* __restrict__ out,
                                 const float* __restrict__ weight) {
    int i = blockIdx.x * blockDim.x + threadIdx.x;   // float4 index over NN*CC
    if (i >= NN * CC / 4) return;
    int c4 = i % 12;
    int cbase = c4 * 4;
    float4 v = reinterpret_cast<const float4*>(g_h1f)[i];
    reinterpret_cast<uint2*>(hdst)[i] = pack_half4(v);
    float w0 = __ldg(&weight[(cbase + 0) * SS]);
    float w1 = __ldg(&weight[(cbase + 1) * SS]);
    float w2 = __ldg(&weight[(cbase + 2) * SS]);
    float w3 = __ldg(&weight[(cbase + 3) * SS]);
    float4 o;
    o.x = v.x * w0; o.y = v.y * w1; o.z = v.z * w2; o.w = v.w * w3;
    reinterpret_cast<float4*>(out)[i] = o;   // first write: no read needed
}

// ---------- steps 1..9: fp16 CSC gather SpMM, fp32 accumulate, fused axpy ----------
// 12 threads per node, thread c4 owns channels [c4*4, c4*4+4); edge loop unrolled x4
__global__ void gather_kernel(const __half* __restrict__ hsrc,
                              __half* __restrict__ hdst,
                              float* __restrict__ out,
                              const float* __restrict__ weight,
                              int s, int write_h) {
    int node = blockIdx.x * 16 + threadIdx.x / 12;
    int c4 = threadIdx.x % 12;
    if (node >= NN) return;
    int beg = g_off[node], end = g_off[node + 1];
    float4 acc = make_float4(0.f, 0.f, 0.f, 0.f);

    int j = beg;
    int n4 = beg + (((end - beg) >> 2) << 2);
    for (; j < n4; j += 4) {
        float2 e0 = __ldg(&g_csc[j]);
        float2 e1 = __ldg(&g_csc[j + 1]);
        float2 e2 = __ldg(&g_csc[j + 2]);
        float2 e3 = __ldg(&g_csc[j + 3]);
        uint2 r0 = __ldg(reinterpret_cast<const uint2*>(hsrc + __float_as_int(e0.x) * CC) + c4);
        uint2 r1 = __ldg(reinterpret_cast<const uint2*>(hsrc + __float_as_int(e1.x) * CC) + c4);
        uint2 r2 = __ldg(reinterpret_cast<const uint2*>(hsrc + __float_as_int(e2.x) * CC) + c4);
        uint2 r3 = __ldg(reinterpret_cast<const uint2*>(hsrc + __float_as_int(e3.x) * CC) + c4);
        float2 a0 = __half22float2(*reinterpret_cast<__half2*>(&r0.x));
        float2 b0 = __half22float2(*reinterpret_cast<__half2*>(&r0.y));
        float2 a1 = __half22float2(*reinterpret_cast<__half2*>(&r1.x));
        float2 b1 = __half22float2(*reinterpret_cast<__half2*>(&r1.y));
        float2 a2 = __half22float2(*reinterpret_cast<__half2*>(&r2.x));
        float2 b2 = __half22float2(*reinterpret_cast<__half2*>(&r2.y));
        float2 a3 = __half22float2(*reinterpret_cast<__half2*>(&r3.x));
        float2 b3 = __half22float2(*reinterpret_cast<__half2*>(&r3.y));
        acc.x = fmaf(e0.y, a0.x, acc.x);
        acc.y = fmaf(e0.y, a0.y, acc.y);
        acc.z = fmaf(e0.y, b0.x, acc.z);
        acc.w = fmaf(e0.y, b0.y, acc.w);
        acc.x = fmaf(e1.y, a1.x, acc.x);
        acc.y = fmaf(e1.y, a1.y, acc.y);
        acc.z = fmaf(e1.y, b1.x, acc.z);
        acc.w = fmaf(e1.y, b1.y, acc.w);
        acc.x = fmaf(e2.y, a2.x, acc.x);
        acc.y = fmaf(e2.y, a2.y, acc.y);
        acc.z = fmaf(e2.y, b2.x, acc.z);
        acc.w = fmaf(e2.y, b2.y, acc.w);
        acc.x = fmaf(e3.y, a3.x, acc.x);
        acc.y = fmaf(e3.y, a3.y, acc.y);
        acc.z = fmaf(e3.y, b3.x, acc.z);
        acc.w = fmaf(e3.y, b3.y, acc.w);
    }
    for (; j < end; j++) {
        float2 ed = __ldg(&g_csc[j]);
        uint2 raw = __ldg(reinterpret_cast<const uint2*>(hsrc + __float_as_int(ed.x) * CC) + c4);
        float2 fa = __half22float2(*reinterpret_cast<__half2*>(&raw.x));
        float2 fb = __half22float2(*reinterpret_cast<__half2*>(&raw.y));
        acc.x = fmaf(ed.y, fa.x, acc.x);
        acc.y = fmaf(ed.y, fa.y, acc.y);
        acc.z = fmaf(ed.y, fb.x, acc.z);
        acc.w = fmaf(ed.y, fb.y, acc.w);
    }

    if (write_h)
        reinterpret_cast<uint2*>(hdst + node * CC)[c4] = pack_half4(acc);
    int cbase = c4 * 4;
    float w0 = __ldg(&weight[(cbase + 0) * SS + s]);
    float w1 = __ldg(&weight[(cbase + 1) * SS + s]);
    float w2 = __ldg(&weight[(cbase + 2) * SS + s]);
    float w3 = __ldg(&weight[(cbase + 3) * SS + s]);
    float4 o = reinterpret_cast<float4*>(out + node * CC)[c4];
    o.x += acc.x * w0; o.y += acc.y * w1; o.z += acc.z * w2; o.w += acc.w * w3;
    reinterpret_cast<float4*>(out + node * CC)[c4] = o;
}

extern "C" void kernel_launch(void* const* d_in, const int* in_sizes, int n_in,
                              void* d_out, int out_size) {
    const int*   ei     = (const int*)d_in[0];    // [2, E]
    const float* ea     = (const float*)d_in[1];  // [E]
    const int*   target = (const int*)d_in[2];    // [N]
    const float* weight = (const float*)d_in[3];  // [C, S]
    float* out = (float*)d_out;                   // [N, C]

    void* p_deg;  cudaGetSymbolAddress(&p_deg,  g_deg);
    void* p_cnt;  cudaGetSymbolAddress(&p_cnt,  g_cnt);
    void* p_h1f;  cudaGetSymbolAddress(&p_h1f,  g_h1f);
    void* p_hA;   cudaGetSymbolAddress(&p_hA,   g_hA);
    void* p_hB;   cudaGetSymbolAddress(&p_hB,   g_hB);

    cudaMemsetAsync(p_deg, 0, NN * sizeof(float), 0);
    cudaMemsetAsync(p_cnt, 0, NN * sizeof(int), 0);
    cudaMemsetAsync(p_h1f, 0, (size_t)NN * CC * sizeof(float), 0);

    count_deg_kernel<<<(EE / 2 + 255) / 256, 256>>>(ei, ea);
    scan_kernel<<<1, 1024>>>();
    build_csc_kernel<<<(EE + 255) / 256, 256>>>(ei, ea, target);

    __half* hA = (__half*)p_hA;
    __half* hB = (__half*)p_hB;

    // finalize step 1: convert scattered h1 to fp16, init out with w[:,0]
    finalize0_kernel<<<(NN * CC / 4 + 255) / 256, 256>>>(hA, out, weight);

    const int node_blocks = (NN + 15) / 16;
    __half* hcur = hA;
    __half* hnxt = hB;
    for (int s = 1; s < SS; s++) {
        gather_kernel<<<node_blocks, 192>>>(hcur, hnxt, out, weight, s,
                                            (s < SS - 1) ? 1 : 0);
        __half* t = hcur; hcur = hnxt; hnxt = t;
    }
}